// round 5
// baseline (speedup 1.0000x reference)
#include <cuda_runtime.h>
#include <cuda_bf16.h>
#include <math.h>

#define TPB 256
#define CPT 4
#define CW  (TPB*CPT)   // 1024 columns per tile
#define RH  128         // rows per tile
#define MAX_BLOCKS 1024
#define EPS 1e-7f

__device__ double             g_part_sq[MAX_BLOCKS];
__device__ unsigned long long g_part_cnt[MAX_BLOCKS];
__device__ double             g_bce_part[64];
__device__ unsigned int       g_ticket;

__device__ __forceinline__ float logit_f(float t) {
    float p = fminf(fmaxf(t, EPS), 1.0f - EPS);
    return logf(p) - log1pf(-p);
}

__global__ void fused_kernel(const float* __restrict__ pred,
                             const float* __restrict__ psi,
                             const int*   __restrict__ flag,
                             float*       __restrict__ out, int n)
{
    const int tid = threadIdx.x;
    const int bx = blockIdx.x, by = blockIdx.y;
    const int bid = by * gridDim.x + bx;
    const int c0 = bx * CW, r0 = by * RH;

    const int  cmax   = min(c0 + CW, n);                       // exclusive
    const bool active = (c0 < n) && (r0 < n) && (cmax - 1 > r0); // tile has j>i pairs

    if (active) {
        __shared__ float s_u[RH], s_p[RH];
        float uc[CPT], pc[CPT];
        bool  ok[CPT];
        float bce = 0.f;
        const bool do_bce = (r0 == c0);   // one straddle-top block per column group
        const int  cb = c0 + tid * CPT;

        #pragma unroll
        for (int k = 0; k < CPT; k++) {
            int c = cb + k;
            ok[k] = (c < n);
            float x = ok[k] ? pred[c] : 0.f;
            float t = ok[k] ? psi[c]  : 0.f;
            if (do_bce && ok[k])
                bce += fmaxf(x, 0.f) - x * t + log1pf(expf(-fabsf(x)));
            uc[k] = x - logit_f(t);
            pc[k] = t;
        }
        if (tid < RH) {
            int r = r0 + tid;
            float x = (r < n) ? pred[r] : 0.f;
            float t = (r < n) ? psi[r]  : 0.f;
            s_p[tid] = t;
            s_u[tid] = x - logit_f(t);
        }
        __syncthreads();

        const int rend = min(RH, n - r0);
        float acc = 0.f;
        int   cnt = 0;
        if (c0 >= r0 + RH) {
            // full tile: every (row, col) has col > row
            #pragma unroll 2
            for (int i = 0; i < rend; i++) {
                float ui = s_u[i], pi = s_p[i];
                #pragma unroll
                for (int k = 0; k < CPT; k++) {
                    float dp = pi - pc[k];
                    float du = ui - uc[k];
                    if (ok[k] & (fabsf(dp) >= 0.05f)) { acc = fmaf(du, du, acc); cnt++; }
                }
            }
        } else {
            // diagonal straddle tile: predicate col > row
            for (int i = 0; i < rend; i++) {
                float ui = s_u[i], pi = s_p[i];
                int gi = r0 + i;
                #pragma unroll
                for (int k = 0; k < CPT; k++) {
                    float dp = pi - pc[k];
                    float du = ui - uc[k];
                    bool v = ok[k] & ((cb + k) > gi) & (fabsf(dp) >= 0.05f);
                    if (v) { acc = fmaf(du, du, acc); cnt++; }
                }
            }
        }

        // block reduction
        #pragma unroll
        for (int o = 16; o; o >>= 1) {
            acc += __shfl_xor_sync(0xffffffffu, acc, o);
            cnt += __shfl_xor_sync(0xffffffffu, cnt, o);
            bce += __shfl_xor_sync(0xffffffffu, bce, o);
        }
        __shared__ float wa[TPB/32], wb[TPB/32];
        __shared__ int   wc[TPB/32];
        if ((tid & 31) == 0) { wa[tid>>5] = acc; wc[tid>>5] = cnt; wb[tid>>5] = bce; }
        __syncthreads();
        if (tid == 0) {
            float A = 0.f, B = 0.f; long long C = 0;
            #pragma unroll
            for (int w = 0; w < TPB/32; w++) { A += wa[w]; C += wc[w]; B += wb[w]; }
            g_part_sq[bid]  = (double)A;
            g_part_cnt[bid] = (unsigned long long)C;
            if (do_bce) g_bce_part[bx] = (double)B;
        }
    }

    // ---- last-block finalize ----
    __threadfence();
    __shared__ unsigned s_tick;
    if (tid == 0) s_tick = atomicAdd(&g_ticket, 1u);
    __syncthreads();
    if (s_tick == gridDim.x * gridDim.y - 1) {
        const int T = gridDim.x * gridDim.y;
        double sq = 0.0, bce = 0.0;
        unsigned long long cnt = 0ull;
        for (int s = tid; s < T; s += TPB) { sq += g_part_sq[s]; cnt += g_part_cnt[s]; }
        if (tid < (int)gridDim.x) bce = g_bce_part[tid];
        #pragma unroll
        for (int o = 16; o; o >>= 1) {
            sq  += __shfl_xor_sync(0xffffffffu, sq,  o);
            bce += __shfl_xor_sync(0xffffffffu, bce, o);
            cnt += __shfl_xor_sync(0xffffffffu, cnt, o);
        }
        __shared__ double ra[TPB/32], rb[TPB/32];
        __shared__ unsigned long long rc[TPB/32];
        if ((tid & 31) == 0) { ra[tid>>5] = sq; rb[tid>>5] = bce; rc[tid>>5] = cnt; }
        __syncthreads();
        if (tid == 0) {
            double S = 0.0, Bc = 0.0; unsigned long long C = 0ull;
            #pragma unroll
            for (int w = 0; w < TPB/32; w++) { S += ra[w]; Bc += rb[w]; C += rc[w]; }
            // upper-triangle sq and cnt are both exactly half the full sums:
            // the ratio is unchanged, and cnt>0 <=> n_valid>0.
            double loss = Bc / (double)n;
            if (!(*flag) && C > 0ull) loss += 10.0 * (S / (double)C);
            out[0] = (float)loss;
            g_ticket = 0u;   // reset for next graph replay
        }
    }
}

extern "C" void kernel_launch(void* const* d_in, const int* in_sizes, int n_in,
                              void* d_out, int out_size) {
    const float* pred = (const float*)d_in[0];
    const float* psi  = (const float*)d_in[1];
    const int*   flag = (const int*)d_in[2];
    float*       out  = (float*)d_out;
    const int n = in_sizes[0];

    dim3 grid((n + CW - 1) / CW, (n + RH - 1) / RH);
    fused_kernel<<<grid, TPB>>>(pred, psi, flag, out, n);
}

// round 6
// speedup vs baseline: 1.1856x; 1.1856x over previous
#include <cuda_runtime.h>
#include <cuda_bf16.h>
#include <math.h>

#define TPB  256
#define CPT  8
#define CW   (TPB*CPT)    // 2048 columns per group
#define RCH  8            // rows per unit
#define GRID 592          // 4 blocks per SM, one wave
#define MAXG 32
#define EPS  1e-7f

__device__ double             g_sq;
__device__ double             g_bce;
__device__ unsigned long long g_cnt;
__device__ unsigned int       g_done;

__device__ __forceinline__ float logit_fast(float t) {
    float p = fminf(fmaxf(t, EPS), 1.0f - EPS);
    return __logf(p) - __logf(1.0f - p);
}

// body: dp/du + threshold predicate (+ optional col>row check), 5-6 slots/pair
#define PAIR_BODY(EXTRA)                                        \
    {                                                           \
        float2 rp = s_up[i];                                    \
        _Pragma("unroll")                                       \
        for (int k = 0; k < CPT; k++) {                         \
            float dp = rp.y - pc[k];                            \
            float du = rp.x - uc[k];                            \
            bool v = (fabsf(dp) >= 0.05f) EXTRA;                \
            if (v) { acc = fmaf(du, du, acc); cnt++; }          \
        }                                                       \
    }

__global__ void __launch_bounds__(TPB)
fused(const float* __restrict__ pred, const float* __restrict__ psi,
      const int* __restrict__ flag, float* __restrict__ out, int n)
{
    __shared__ float2 s_up[RCH];
    __shared__ double s_ra[TPB/32], s_rb[TPB/32];
    __shared__ unsigned long long s_rc[TPB/32];

    const int tid = threadIdx.x;
    const int b   = blockIdx.x;
    const int G   = gridDim.x;
    const int ncolg = (n + CW - 1) / CW;

    // triangle unit list: group g owns cols [g*CW, cend), rows [0, cend)
    int chunksA[MAXG];
    int U = 0;
    for (int g = 0; g < ncolg; g++) {
        int cend = min((g + 1) * CW, n);
        chunksA[g] = (cend + RCH - 1) / RCH;
        U += chunksA[g];
    }
    const int u0 = (int)((long long)b       * U / G);
    const int u1 = (int)((long long)(b + 1) * U / G);

    int g = 0, chunk = u0;
    while (g < ncolg && chunk >= chunksA[g]) { chunk -= chunksA[g]; g++; }

    double dacc = 0.0, dbce = 0.0;
    unsigned long long cnt_tot = 0ull;
    float uc[CPT], pc[CPT];
    int loaded_g = -1;

    for (int u = u0; u < u1; u++) {
        const int c0   = g * CW;
        const int cend = min(c0 + CW, n);
        const int cb   = c0 + tid * CPT;

        if (g != loaded_g) {               // column registers (rare reload)
            loaded_g = g;
            #pragma unroll
            for (int k = 0; k < CPT; k++) {
                int c = cb + k;
                if (c < n) {
                    float x = pred[c], t = psi[c];
                    pc[k] = t;
                    uc[k] = x - logit_fast(t);
                } else {
                    pc[k] = __int_as_float(0x7fffffff); // NaN -> predicate false
                    uc[k] = 0.f;
                }
            }
        }
        if (chunk == 0) {                  // BCE: exactly once per column group
            float bces = 0.f;
            #pragma unroll
            for (int k = 0; k < CPT; k++) {
                int c = cb + k;
                if (c < n) {
                    float x = pred[c], t = psi[c];
                    bces += fmaxf(x, 0.f) - x * t + log1pf(expf(-fabsf(x)));
                }
            }
            dbce += (double)bces;
        }

        const int r0   = chunk * RCH;
        const int rend = min(RCH, cend - r0);

        __syncthreads();
        if (tid < rend) {
            int r = r0 + tid;
            float x = pred[r], t = psi[r];
            s_up[tid] = make_float2(x - logit_fast(t), t);
        }
        __syncthreads();

        float acc = 0.f;
        int   cnt = 0;
        if (r0 + rend <= c0) {             // full tile: all cols > all rows
            if (rend == RCH) {
                #pragma unroll
                for (int i = 0; i < RCH; i++) PAIR_BODY()
            } else {
                for (int i = 0; i < rend; i++) PAIR_BODY()
            }
        } else {                           // straddle: need col > row
            if (rend == RCH) {
                #pragma unroll
                for (int i = 0; i < RCH; i++) PAIR_BODY(&& (cb + k > r0 + i))
            } else {
                for (int i = 0; i < rend; i++) PAIR_BODY(&& (cb + k > r0 + i))
            }
        }
        dacc   += (double)acc;
        cnt_tot += (unsigned long long)cnt;

        if (++chunk == chunksA[g]) { chunk = 0; g++; }
    }

    // block reduction
    #pragma unroll
    for (int o = 16; o; o >>= 1) {
        dacc    += __shfl_xor_sync(0xffffffffu, dacc, o);
        dbce    += __shfl_xor_sync(0xffffffffu, dbce, o);
        cnt_tot += __shfl_xor_sync(0xffffffffu, cnt_tot, o);
    }
    if ((tid & 31) == 0) { s_ra[tid >> 5] = dacc; s_rb[tid >> 5] = dbce; s_rc[tid >> 5] = cnt_tot; }
    __syncthreads();
    if (tid == 0) {
        double S = 0.0, B = 0.0; unsigned long long C = 0ull;
        #pragma unroll
        for (int w = 0; w < TPB/32; w++) { S += s_ra[w]; B += s_rb[w]; C += s_rc[w]; }
        atomicAdd(&g_sq, S);
        atomicAdd(&g_bce, B);
        atomicAdd(&g_cnt, C);
        __threadfence();
        unsigned t = atomicAdd(&g_done, 1u);
        if (t == (unsigned)(G - 1)) {      // last block finalizes
            __threadfence();
            double  Sf = atomicAdd(&g_sq, 0.0);
            double  Bf = atomicAdd(&g_bce, 0.0);
            unsigned long long Cf = atomicAdd(&g_cnt, 0ull);
            // upper triangle: sq and cnt both exactly halved -> ratio unchanged
            double loss = Bf / (double)n;
            if (!(*flag) && Cf > 0ull) loss += 10.0 * (Sf / (double)Cf);
            *out = (float)loss;
            __threadfence();
            g_sq = 0.0; g_bce = 0.0; g_cnt = 0ull; g_done = 0u; // reset for replay
        }
    }
}

extern "C" void kernel_launch(void* const* d_in, const int* in_sizes, int n_in,
                              void* d_out, int out_size) {
    const float* pred = (const float*)d_in[0];
    const float* psi  = (const float*)d_in[1];
    const int*   flag = (const int*)d_in[2];
    float*       out  = (float*)d_out;
    const int n = in_sizes[0];

    fused<<<GRID, TPB>>>(pred, psi, flag, out, n);
}